// round 8
// baseline (speedup 1.0000x reference)
#include <cuda_runtime.h>
#include <float.h>

typedef unsigned long long ull;

#define NB   8
#define NLQ  512
#define NL   4096
#define ND   64
#define TQ   8
#define NTHREADS 512
#define NCTAS  (NB * (NLQ/TQ))     // 512

#define TKS 128                    // score-group tile
#define NTS (NL/TKS)               // 32
#define TKM 32                     // mean-group tile
#define NTM (NL/TKM)               // 128

#define KPLANE 2564      // floats per K quarter-plane (128 rows x 20 + 4 pad)
#define KROW   20        // K plane row stride (16 data + 4 pad)
#define KBUF   (4*KPLANE)          // 10256 floats per K buffer
#define VSTR   64        // V rows unpadded
#define QQS    200       // qT quarter-block stride (16*12 + 8)
#define NWORDS (NL/32)   // 128 mask words per row

// smem offsets (floats)
#define OFF_KS   0                             // 2*KBUF = 20512
#define OFF_VS   (OFF_KS + 2*KBUF)             // 2*32*64 = 4096
#define OFF_KM   (OFF_VS + 2*TKM*VSTR)         // 64 words
#define OFF_VM   (OFF_KM + 64)                 // 16 words
#define OFF_QT   (OFF_VM + 16)                 // 800
#define OFF_MSUM (OFF_QT + 4*QQS)              // 512
#define OFF_CNT  (OFF_MSUM + TQ*ND)            // 8
#define SMEM_FLOATS (OFF_CNT + TQ)             // 26008
#define SMEM_BYTES  (SMEM_FLOATS * 4)          // 104032 -> 2 CTAs/SM

// packed fp32x2 ops (sm_103a)
#define F32X2_FMA(d,a,b)  asm("fma.rn.f32x2 %0, %1, %2, %0;" : "+l"(d) : "l"(a), "l"(b))
#define F32X2_ADD(d,a,b)  asm("add.rn.f32x2 %0, %1, %2;"     : "=l"(d) : "l"(a), "l"(b))
#define F32X2_PACK(d,lo,hi)   asm("mov.b64 %0, {%1, %2};" : "=l"(d) : "f"(lo), "f"(hi))
#define F32X2_UNPACK(lo,hi,s) asm("mov.b64 {%0, %1}, %2;" : "=f"(lo), "=f"(hi) : "l"(s))

#define ONE2 0x3F8000003F800000ULL

__device__ __forceinline__ void cp16(void* s, const void* g) {
    unsigned sa = (unsigned)__cvta_generic_to_shared(s);
    asm volatile("cp.async.cg.shared.global [%0], [%1], 16;" :: "r"(sa), "l"(g));
}
__device__ __forceinline__ void cp4(void* s, const void* g) {
    unsigned sa = (unsigned)__cvta_generic_to_shared(s);
    asm volatile("cp.async.ca.shared.global [%0], [%1], 4;" :: "r"(sa), "l"(g));
}
#define CP_COMMIT() asm volatile("cp.async.commit_group;" ::: "memory")
#define CP_WAIT0()  asm volatile("cp.async.wait_group 0;" ::: "memory")
#define BARG(id)    asm volatile("bar.sync %0, 256;" :: "r"(id) : "memory")

// global scratch
__device__ float    g_sc[(size_t)NCTAS * TQ * NL];      // 64 MB (L2-resident per wave)
__device__ unsigned g_mbits[(size_t)NB * NLQ * NWORDS]; // 2 MB bit mask
__device__ int      g_mask_mode;                        // 0=u8, 1=i32, 2=f32

__global__ void detect_mask_kernel(const unsigned int* __restrict__ m) {
    int allle1 = 1, allf = 1;
    for (int i = 0; i < 32; ++i) {
        unsigned w = m[i];
        if (w > 1u) allle1 = 0;
        if (w != 0u && w != 0x3F800000u) allf = 0;
    }
    g_mask_mode = allf ? 2 : (allle1 ? 1 : 0);
}

// pack mask -> bits: one thread builds one 32-bit word
__global__ __launch_bounds__(256)
void maskbits_kernel(const void* __restrict__ mg) {
    int tid = blockIdx.x * 256 + threadIdx.x;      // 0 .. 524287
    unsigned w = 0;
    if (g_mask_mode == 0) {
        const uint4* p = (const uint4*)((const char*)mg + (size_t)tid * 32);
        uint4 a = p[0], b2 = p[1];
        unsigned v[8] = {a.x, a.y, a.z, a.w, b2.x, b2.y, b2.z, b2.w};
        #pragma unroll
        for (int i = 0; i < 8; ++i)
            #pragma unroll
            for (int j = 0; j < 4; ++j)
                w |= (((v[i] >> (8 * j)) & 0xFFu) ? 1u : 0u) << (i * 4 + j);
    } else {
        const uint4* p = (const uint4*)((const char*)mg + (size_t)tid * 128);
        #pragma unroll
        for (int i = 0; i < 8; ++i) {
            uint4 x = p[i];
            w |= (x.x ? 1u : 0u) << (i * 4 + 0);
            w |= (x.y ? 1u : 0u) << (i * 4 + 1);
            w |= (x.z ? 1u : 0u) << (i * 4 + 2);
            w |= (x.w ? 1u : 0u) << (i * 4 + 3);
        }
    }
    g_mbits[tid] = w;
}

__global__ __launch_bounds__(NTHREADS, 2)
void ga_kernel(const float* __restrict__ qg, const float* __restrict__ kg,
               const float* __restrict__ vg, float* __restrict__ out)
{
    extern __shared__ float smem[];
    float*    k_s  = smem + OFF_KS;
    float*    v_s  = smem + OFF_VS;
    unsigned* km   = (unsigned*)(smem + OFF_KM);
    unsigned* vm   = (unsigned*)(smem + OFF_VM);
    float*    qT   = smem + OFF_QT;
    float*    msum = smem + OFF_MSUM;
    float*    cnts = smem + OFF_CNT;

    const int t    = threadIdx.x;
    const int wid  = t >> 5;
    const int lane = t & 31;
    const int b    = blockIdx.x >> 6;
    const int q0   = (blockIdx.x & 63) * TQ;

    float* gsc = g_sc + (size_t)blockIdx.x * (TQ * NL);
    const unsigned* mb = g_mbits + (size_t)(b * NLQ + q0) * NWORDS;

    float c0 = 0.f, c1 = 0.f;

    if (wid < 8) {
        // =================== SCORE GROUP (threads 0..255) ===================
        const int t2 = t;
        // stage qT: qT[(d>>4)*QQS + (d&15)*12 + (q>>2)*4 + (q&3)]
        #pragma unroll
        for (int e = 0; e < 2; ++e) {
            int idx = t2 * 2 + e;
            int d = idx >> 3, q = idx & 7;
            qT[(d >> 4) * QQS + (d & 15) * 12 + (q >> 2) * 4 + (q & 3)] =
                qg[((size_t)(b * NLQ + q0 + q)) * ND + d];
        }

        const char* kbase = (const char*)(kg + (size_t)b * NL * ND);
        // producer map: chunk c = t2&15 of row; dh = c>>2, within-quarter (c&3)*4
        const int pc   = t2 & 15;
        const int pdh  = pc >> 2;
        const int pq4  = (pc & 3) * 4;
        const int pr0  = t2 >> 4;             // row base, +16 per r

        {
            #pragma unroll
            for (int r = 0; r < 8; ++r) {
                int row = pr0 + 16 * r;
                cp16(k_s + pdh * KPLANE + row * KROW + pq4,
                     kbase + (size_t)row * 256 + pc * 16);
            }
            if (t2 < 8) cp16(km + t2 * 4, mb + t2 * NWORDS + 0);
            CP_COMMIT();
        }

        // lane layout: kg (4 key-groups of 4) x qh (2 query-halves) x dh (4 dim-quarters)
        const int kg_ = lane >> 3;
        const int qh  = (lane >> 2) & 1;
        const int dh  = lane & 3;
        const int kloc = wid * 16 + kg_ * 4;      // first of lane's 4 keys in tile
        const int kword = wid >> 1;               // key>>5 within tile, const per warp
        const float* qb2 = qT + dh * QQS + qh * 4;

        for (int tile = 0; tile < NTS; ++tile) {
            CP_WAIT0();
            BARG(1);
            if (tile + 1 < NTS) {
                float* kd = k_s + ((tile + 1) & 1) * KBUF;
                const char* kt = kbase + (size_t)(tile + 1) * TKS * 256;
                #pragma unroll
                for (int r = 0; r < 8; ++r) {
                    int row = pr0 + 16 * r;
                    cp16(kd + pdh * KPLANE + row * KROW + pq4,
                         kt + (size_t)row * 256 + pc * 16);
                }
                if (t2 < 8)
                    cp16(km + ((tile + 1) & 1) * 32 + t2 * 4,
                         mb + t2 * NWORDS + (tile + 1) * 4);
                CP_COMMIT();
            }

            const float* kq = k_s + (tile & 1) * KBUF + dh * KPLANE + kloc * KROW;
            ull a00=0, a01=0, a10=0, a11=0, a20=0, a21=0, a30=0, a31=0;
            #pragma unroll
            for (int s4 = 0; s4 < 4; ++s4) {
                float4 k0v = *(const float4*)(kq + 0 * KROW + 4 * s4);
                float4 k1v = *(const float4*)(kq + 1 * KROW + 4 * s4);
                float4 k2v = *(const float4*)(kq + 2 * KROW + 4 * s4);
                float4 k3v = *(const float4*)(kq + 3 * KROW + 4 * s4);
                #pragma unroll
                for (int j = 0; j < 4; ++j) {
                    ulonglong2 qv = *(const ulonglong2*)(qb2 + (s4 * 4 + j) * 12);
                    float f0 = (j==0)?k0v.x:(j==1)?k0v.y:(j==2)?k0v.z:k0v.w;
                    float f1 = (j==0)?k1v.x:(j==1)?k1v.y:(j==2)?k1v.z:k1v.w;
                    float f2 = (j==0)?k2v.x:(j==1)?k2v.y:(j==2)?k2v.z:k2v.w;
                    float f3 = (j==0)?k3v.x:(j==1)?k3v.y:(j==2)?k3v.z:k3v.w;
                    ull p0, p1, p2, p3;
                    F32X2_PACK(p0, f0, f0);
                    F32X2_PACK(p1, f1, f1);
                    F32X2_PACK(p2, f2, f2);
                    F32X2_PACK(p3, f3, f3);
                    F32X2_FMA(a00, p0, qv.x); F32X2_FMA(a01, p0, qv.y);
                    F32X2_FMA(a10, p1, qv.x); F32X2_FMA(a11, p1, qv.y);
                    F32X2_FMA(a20, p2, qv.x); F32X2_FMA(a21, p2, qv.y);
                    F32X2_FMA(a30, p3, qv.x); F32X2_FMA(a31, p3, qv.y);
                }
            }
            // reduce over dh (lane bits 0-1)
            ull o;
            #pragma unroll
            for (int off = 1; off <= 2; off <<= 1) {
                o = __shfl_xor_sync(0xffffffffu, a00, off); F32X2_ADD(a00, a00, o);
                o = __shfl_xor_sync(0xffffffffu, a01, off); F32X2_ADD(a01, a01, o);
                o = __shfl_xor_sync(0xffffffffu, a10, off); F32X2_ADD(a10, a10, o);
                o = __shfl_xor_sync(0xffffffffu, a11, off); F32X2_ADD(a11, a11, o);
                o = __shfl_xor_sync(0xffffffffu, a20, off); F32X2_ADD(a20, a20, o);
                o = __shfl_xor_sync(0xffffffffu, a21, off); F32X2_ADD(a21, a21, o);
                o = __shfl_xor_sync(0xffffffffu, a30, off); F32X2_ADD(a30, a30, o);
                o = __shfl_xor_sync(0xffffffffu, a31, off); F32X2_ADD(a31, a31, o);
            }
            if (dh == 0) {
                float f[4][4];
                F32X2_UNPACK(f[0][0], f[0][1], a00); F32X2_UNPACK(f[0][2], f[0][3], a01);
                F32X2_UNPACK(f[1][0], f[1][1], a10); F32X2_UNPACK(f[1][2], f[1][3], a11);
                F32X2_UNPACK(f[2][0], f[2][1], a20); F32X2_UNPACK(f[2][2], f[2][3], a21);
                F32X2_UNPACK(f[3][0], f[3][1], a30); F32X2_UNPACK(f[3][2], f[3][3], a31);
                const unsigned* kmc = km + (tile & 1) * 32;
                const int l0 = tile * TKS;
                #pragma unroll
                for (int qi = 0; qi < 4; ++qi) {
                    const int q = qh * 4 + qi;
                    unsigned w = kmc[q * 4 + kword];
                    float* gr = gsc + q * NL + l0 + kloc;
                    #pragma unroll
                    for (int j = 0; j < 4; ++j) {
                        unsigned bit = (w >> ((kloc + j) & 31)) & 1u;
                        gr[j] = bit ? f[j][qi] * 0.125f : -FLT_MAX;
                    }
                }
            }
        }

        __threadfence_block();
        BARG(1);   // all scores written by score group

        // ---- top-32 + softmax + gather for query q = wid ----
        const int q = wid;
        const float* row = gsc + q * NL;

        float v0 = -FLT_MAX, v1 = -FLT_MAX, v2 = -FLT_MAX, v3 = -FLT_MAX;
        int   i0 = NL, i1 = NL, i2 = NL, i3 = NL;
        for (int i = lane; i < NL; i += 32) {
            float x = row[i];
            if (x > v3) {
                if (x > v1) {
                    if (x > v0) { v3=v2;i3=i2; v2=v1;i2=i1; v1=v0;i1=i0; v0=x;i0=i; }
                    else        { v3=v2;i3=i2; v2=v1;i2=i1; v1=x;i1=i; }
                } else {
                    if (x > v2) { v3=v2;i3=i2; v2=x;i2=i; }
                    else        { v3=x;i3=i; }
                }
            }
        }

        float myval = -FLT_MAX;
        int   myidx = NL;
        for (int s = 0; s < 32; ++s) {
            float cv = v0; int ci = i0;
            #pragma unroll
            for (int off = 16; off; off >>= 1) {
                float ov = __shfl_xor_sync(0xffffffffu, cv, off);
                int   oi = __shfl_xor_sync(0xffffffffu, ci, off);
                if (ov > cv || (ov == cv && oi < ci)) { cv = ov; ci = oi; }
            }
            if (lane == s) { myval = cv; myidx = ci; }
            if (v0 == cv && i0 == ci) {
                v0 = v1; i0 = i1; v1 = v2; i1 = i2; v2 = v3; i2 = i3;
                v3 = -FLT_MAX; i3 = NL;
                if (v0 == -FLT_MAX && cv > -FLT_MAX) {
                    float nv = -FLT_MAX; int ni = NL;
                    for (int i = lane; i < NL; i += 32) {
                        float x = row[i];
                        if (x < cv && x > nv) { nv = x; ni = i; }
                    }
                    v0 = nv; i0 = ni;
                }
            }
        }

        bool  valid = (myval > -1e37f) && (myidx < NL);
        float mmax  = valid ? myval : -FLT_MAX;
        #pragma unroll
        for (int off = 16; off; off >>= 1)
            mmax = fmaxf(mmax, __shfl_xor_sync(0xffffffffu, mmax, off));
        float e  = valid ? __expf(myval - mmax) : 0.f;
        float es = e;
        #pragma unroll
        for (int off = 16; off; off >>= 1)
            es += __shfl_xor_sync(0xffffffffu, es, off);
        float attn = (es > 0.f) ? e / es : 0.f;

        const float* vb = vg + (size_t)b * NL * ND;
        #pragma unroll 4
        for (int i = 0; i < 32; ++i) {
            float a   = __shfl_sync(0xffffffffu, attn,  i);
            int   idx = __shfl_sync(0xffffffffu, myidx, i);
            if (a > 0.f && idx < NL) {
                const float* vr2 = vb + (size_t)idx * ND;
                c0 += a * vr2[lane];
                c1 += a * vr2[lane + 32];
            }
        }
    } else {
        // =================== MEAN GROUP (threads 256..511) ==================
        const int t2 = t - 256;
        const int wm = wid - 8;

        const char* vbase = (const char*)(vg + (size_t)b * NL * ND);
        const int fd4 = t2 & 15;
        const int fl0 = t2 >> 4;

        {
            #pragma unroll
            for (int r = 0; r < 2; ++r) {
                int row = fl0 + 16 * r;
                cp16(v_s + row * VSTR + fd4 * 4,
                     vbase + (size_t)row * 256 + fd4 * 16);
            }
            if (t2 < 8) cp4(vm + t2, mb + t2 * NWORDS + 0);
            CP_COMMIT();
        }

        const int c   = lane & 15;
        const int qg2 = (lane >> 4) * 4;
        const int lb  = wm * 4;                 // local row base (4 rows/warp)

        ull accA[4] = {0,0,0,0}, accB[4] = {0,0,0,0};

        for (int tile = 0; tile < NTM; ++tile) {
            CP_WAIT0();
            BARG(2);
            if (tile + 1 < NTM) {
                float* vd = v_s + ((tile + 1) & 1) * (TKM * VSTR);
                const char* vt = vbase + (size_t)(tile + 1) * TKM * 256;
                #pragma unroll
                for (int r = 0; r < 2; ++r) {
                    int row = fl0 + 16 * r;
                    cp16(vd + row * VSTR + fd4 * 4,
                         vt + (size_t)row * 256 + fd4 * 16);
                }
                if (t2 < 8)
                    cp4(vm + ((tile + 1) & 1) * 8 + t2,
                        mb + t2 * NWORDS + (tile + 1));
                CP_COMMIT();
            }

            const float* vbuf = v_s + (tile & 1) * (TKM * VSTR);
            const unsigned* vmc = vm + (tile & 1) * 8;
            unsigned wq0 = vmc[qg2 + 0];
            unsigned wq1 = vmc[qg2 + 1];
            unsigned wq2 = vmc[qg2 + 2];
            unsigned wq3 = vmc[qg2 + 3];
            #pragma unroll
            for (int r = 0; r < 4; ++r) {
                ulonglong2 vv = *(const ulonglong2*)(vbuf + (lb + r) * VSTR + 4 * c);
                ull pm;
                pm = ((wq0 >> (lb + r)) & 1u) ? ONE2 : 0ULL;
                F32X2_FMA(accA[0], pm, vv.x); F32X2_FMA(accB[0], pm, vv.y);
                pm = ((wq1 >> (lb + r)) & 1u) ? ONE2 : 0ULL;
                F32X2_FMA(accA[1], pm, vv.x); F32X2_FMA(accB[1], pm, vv.y);
                pm = ((wq2 >> (lb + r)) & 1u) ? ONE2 : 0ULL;
                F32X2_FMA(accA[2], pm, vv.x); F32X2_FMA(accB[2], pm, vv.y);
                pm = ((wq3 >> (lb + r)) & 1u) ? ONE2 : 0ULL;
                F32X2_FMA(accA[3], pm, vv.x); F32X2_FMA(accB[3], pm, vv.y);
            }
        }

        // publish per-warp partials into v_s (mean group done with tiles)
        BARG(2);
        float* pbuf = v_s + wm * 512;
        #pragma unroll
        for (int j = 0; j < 4; ++j) {
            float g0, g1, g2, g3;
            F32X2_UNPACK(g0, g1, accA[j]);
            F32X2_UNPACK(g2, g3, accB[j]);
            *(float4*)(pbuf + (qg2 + j) * ND + 4 * c) = make_float4(g0, g1, g2, g3);
        }
        BARG(2);
        // reduce partials -> msum (512 elems / 256 threads)
        #pragma unroll
        for (int r = 0; r < 2; ++r) {
            const int jx = t2 * 2 + r;
            float s = 0.f;
            #pragma unroll
            for (int p = 0; p < 8; ++p) s += v_s[p * 512 + jx];
            msum[jx] = s;
        }
        // counts via popc of full mask row (warp wm handles query wm)
        {
            const unsigned* mrow = mb + wm * NWORDS;
            unsigned s = __popc(mrow[lane]) + __popc(mrow[lane + 32]) +
                         __popc(mrow[lane + 64]) + __popc(mrow[lane + 96]);
            #pragma unroll
            for (int off = 16; off; off >>= 1)
                s += __shfl_xor_sync(0xffffffffu, s, off);
            if (lane == 0) cnts[wm] = (float)s;
        }
    }

    __syncthreads();

    if (wid < 8) {
        const int q = wid;
        float cdiv = fmaxf(cnts[q], 1.f);
        size_t orow = ((size_t)(b * NLQ + q0 + q)) * ND;
        out[orow + lane]      = msum[q * ND + lane]      / cdiv + c0;
        out[orow + lane + 32] = msum[q * ND + lane + 32] / cdiv + c1;
    }
}

extern "C" void kernel_launch(void* const* d_in, const int* in_sizes, int n_in,
                              void* d_out, int out_size) {
    const float* q    = (const float*)d_in[0];
    const float* k    = (const float*)d_in[1];
    const float* v    = (const float*)d_in[2];
    const void*  mask = d_in[3];
    float* out = (float*)d_out;

    cudaFuncSetAttribute(ga_kernel, cudaFuncAttributeMaxDynamicSharedMemorySize,
                         SMEM_BYTES);

    detect_mask_kernel<<<1, 1>>>((const unsigned int*)mask);
    maskbits_kernel<<<(NB * NLQ * NWORDS) / 256, 256>>>(mask);
    ga_kernel<<<NCTAS, NTHREADS, SMEM_BYTES>>>(q, k, v, out);
}